// round 1
// baseline (speedup 1.0000x reference)
#include <cuda_runtime.h>
#include <cuda_bf16.h>

#define NN 100000
#define EE 1600000
#define HD 128
#define FIN 64
#define NLAYER 3

// Scratch (device globals: allocation-free rule)
__device__ float g_dinv[NN];
__device__ float g_buf0[(size_t)NN * HD];  // also reused as matvec output (first NN floats)
__device__ float g_buf1[(size_t)NN * HD];

// ---------------- degree / norm ----------------
__global__ void k_deg_init() {
    int i = blockIdx.x * blockDim.x + threadIdx.x;
    if (i < NN) g_dinv[i] = 1.0f;  // self-loop counts as 1
}
__global__ void k_deg_count(const int* __restrict__ dst) {
    int e = blockIdx.x * blockDim.x + threadIdx.x;
    if (e < EE) atomicAdd(&g_dinv[dst[e]], 1.0f);
}
__global__ void k_deg_rsqrt() {
    int i = blockIdx.x * blockDim.x + threadIdx.x;
    if (i < NN) g_dinv[i] = rsqrtf(g_dinv[i]);  // deg >= 1 always (self loop)
}

// ---------------- aggregation (A_hat @ X), F floats per node ----------------
// init: out[i,:] = in[i,:] * dinv[i]^2   (the self-loop term, also zero-inits out)
template <int F>
__global__ void k_agg_init(const float* __restrict__ in, float* __restrict__ out) {
    constexpr int V = F / 4;
    int idx = blockIdx.x * blockDim.x + threadIdx.x;
    if (idx < NN * V) {
        int row = idx / V;
        float di = g_dinv[row];
        float w = di * di;
        float4 v = ((const float4*)in)[idx];
        v.x *= w; v.y *= w; v.z *= w; v.w *= w;
        ((float4*)out)[idx] = v;
    }
}

// edges: one warp per edge, vectorized reduction (no return) into out[dst]
template <int F>
__global__ void k_agg_edges(const float* __restrict__ in,
                            const int* __restrict__ src, const int* __restrict__ dst,
                            float* __restrict__ out) {
    constexpr int V = F / 4;  // float4 lanes used per edge
    int t = blockIdx.x * blockDim.x + threadIdx.x;
    int e = t >> 5;
    int lane = threadIdx.x & 31;
    if (e >= EE) return;
    int s = src[e];
    int d = dst[e];
    float w = g_dinv[s] * g_dinv[d];
    if (lane < V) {
        float4 v = ((const float4*)in)[(size_t)s * V + lane];
        float4* o = ((float4*)out) + (size_t)d * V + lane;
        asm volatile("red.global.add.v4.f32 [%0], {%1,%2,%3,%4};"
                     :: "l"(o), "f"(v.x * w), "f"(v.y * w), "f"(v.z * w), "f"(v.w * w)
                     : "memory");
    }
}

// ---------------- SGEMM: C[N,128] = A[N,K] @ W[K,128] + bias (opt relu) ----------------
// Block tile 128x128, 256 threads, 8x8 per thread, BK=16.
template <int K>
__global__ void __launch_bounds__(256, 2)
k_gemm(const float* __restrict__ A, const float* __restrict__ W,
       const float* __restrict__ bias, float* __restrict__ C, int do_relu) {
    __shared__ float As[16][128];
    __shared__ float Bs[16][128];
    int tid = threadIdx.x;
    int row0 = blockIdx.x * 128;
    int tr = (tid >> 4) * 8;   // 0..120
    int tc = (tid & 15) * 8;   // 0..120

    float acc[8][8];
#pragma unroll
    for (int i = 0; i < 8; i++)
#pragma unroll
        for (int j = 0; j < 8; j++) acc[i][j] = 0.0f;

    for (int k0 = 0; k0 < K; k0 += 16) {
        // A tile: 128 rows x 16 k  -> As[k][r]  (512 float4, 2 per thread)
#pragma unroll
        for (int i = 0; i < 2; i++) {
            int li = tid + i * 256;       // float4 index 0..511
            int r = li >> 2;              // row within tile (4 float4 per row)
            int kk = (li & 3) * 4;
            float4 v = make_float4(0.f, 0.f, 0.f, 0.f);
            int gr = row0 + r;
            if (gr < NN) v = *(const float4*)(A + (size_t)gr * K + k0 + kk);
            As[kk + 0][r] = v.x; As[kk + 1][r] = v.y;
            As[kk + 2][r] = v.z; As[kk + 3][r] = v.w;
        }
        // B tile: 16 k x 128 n -> Bs[k][n]
#pragma unroll
        for (int i = 0; i < 2; i++) {
            int li = tid + i * 256;       // float4 index over 16*32
            int kk = li >> 5;
            int n4 = (li & 31) * 4;
            *(float4*)&Bs[kk][n4] = *(const float4*)(W + (size_t)(k0 + kk) * 128 + n4);
        }
        __syncthreads();
#pragma unroll
        for (int k = 0; k < 16; k++) {
            float ra[8], rb[8];
            *(float4*)&ra[0] = *(const float4*)&As[k][tr];
            *(float4*)&ra[4] = *(const float4*)&As[k][tr + 4];
            *(float4*)&rb[0] = *(const float4*)&Bs[k][tc];
            *(float4*)&rb[4] = *(const float4*)&Bs[k][tc + 4];
#pragma unroll
            for (int i = 0; i < 8; i++)
#pragma unroll
                for (int j = 0; j < 8; j++) acc[i][j] += ra[i] * rb[j];
        }
        __syncthreads();
    }
    // epilogue: bias + optional relu
#pragma unroll
    for (int i = 0; i < 8; i++) {
        int gr = row0 + tr + i;
        if (gr >= NN) continue;
#pragma unroll
        for (int j = 0; j < 8; j += 4) {
            float4 v;
            v.x = acc[i][j + 0] + bias[tc + j + 0];
            v.y = acc[i][j + 1] + bias[tc + j + 1];
            v.z = acc[i][j + 2] + bias[tc + j + 2];
            v.w = acc[i][j + 3] + bias[tc + j + 3];
            if (do_relu) {
                v.x = fmaxf(v.x, 0.f); v.y = fmaxf(v.y, 0.f);
                v.z = fmaxf(v.z, 0.f); v.w = fmaxf(v.w, 0.f);
            }
            *(float4*)(C + (size_t)gr * 128 + tc + j) = v;
        }
    }
}

// ---------------- final layer: matvec (128 -> 1), then F=1 aggregation ----------------
__global__ void k_matvec(const float* __restrict__ A, const float* __restrict__ W3,
                         float* __restrict__ out) {
    __shared__ float w[128];
    int tid = threadIdx.x;
    if (tid < 128) w[tid] = W3[tid];
    __syncthreads();
    int row = blockIdx.x * 8 + (tid >> 5);
    int lane = tid & 31;
    if (row >= NN) return;
    const float* a = A + (size_t)row * 128;
    float s = a[lane] * w[lane] + a[lane + 32] * w[lane + 32]
            + a[lane + 64] * w[lane + 64] + a[lane + 96] * w[lane + 96];
#pragma unroll
    for (int off = 16; off > 0; off >>= 1) s += __shfl_down_sync(0xffffffffu, s, off);
    if (lane == 0) out[row] = s;
}

__global__ void k_final_init(const float* __restrict__ t, const float* __restrict__ b3,
                             float* __restrict__ out) {
    int i = blockIdx.x * blockDim.x + threadIdx.x;
    if (i < NN) {
        float di = g_dinv[i];
        out[i] = t[i] * di * di + b3[0];
    }
}
__global__ void k_final_edges(const float* __restrict__ t, const int* __restrict__ src,
                              const int* __restrict__ dst, float* __restrict__ out) {
    int e = blockIdx.x * blockDim.x + threadIdx.x;
    if (e >= EE) return;
    int s = src[e], d = dst[e];
    atomicAdd(&out[d], t[s] * g_dinv[s] * g_dinv[d]);
}

// ---------------- launch ----------------
extern "C" void kernel_launch(void* const* d_in, const int* in_sizes, int n_in,
                              void* d_out, int out_size) {
    const float* x  = (const float*)d_in[0];
    const int* ei   = (const int*)d_in[1];
    const float* W1 = (const float*)d_in[2];
    const float* b1 = (const float*)d_in[3];
    const float* W2 = (const float*)d_in[4];
    const float* b2 = (const float*)d_in[5];
    const float* W3 = (const float*)d_in[6];
    const float* b3 = (const float*)d_in[7];
    float* out = (float*)d_out;

    const int* src = ei;        // edge_index[0]
    const int* dst = ei + EE;   // edge_index[1]

    float* buf0;  cudaGetSymbolAddress((void**)&buf0, g_buf0);
    float* buf1;  cudaGetSymbolAddress((void**)&buf1, g_buf1);

    // norm
    k_deg_init<<<(NN + 255) / 256, 256>>>();
    k_deg_count<<<(EE + 255) / 256, 256>>>(dst);
    k_deg_rsqrt<<<(NN + 255) / 256, 256>>>();

    // layer 1: aggregate x at F=64, then GEMM 64->128 (+bias,relu)
    k_agg_init<FIN><<<(NN * (FIN / 4) + 255) / 256, 256>>>(x, buf0);
    k_agg_edges<FIN><<<EE / 8, 256>>>(x, src, dst, buf0);
    k_gemm<FIN><<<(NN + 127) / 128, 256>>>(buf0, W1, b1, buf1, 1);

    // hidden layers: aggregate at F=128, then GEMM 128->128 (+bias,relu)
    for (int l = 0; l < NLAYER; l++) {
        k_agg_init<HD><<<(NN * (HD / 4) + 255) / 256, 256>>>(buf1, buf0);
        k_agg_edges<HD><<<EE / 8, 256>>>(buf1, src, dst, buf0);
        k_gemm<HD><<<(NN + 127) / 128, 256>>>(buf0, W2 + (size_t)l * HD * HD,
                                              b2 + (size_t)l * HD, buf1, 1);
    }

    // final layer: matvec 128->1 first, then F=1 aggregation (+b3)
    k_matvec<<<(NN + 7) / 8, 256>>>(buf1, W3, buf0);
    k_final_init<<<(NN + 255) / 256, 256>>>(buf0, b3, out);
    k_final_edges<<<(EE + 255) / 256, 256>>>(buf0, src, dst, out);
}

// round 2
// speedup vs baseline: 1.8834x; 1.8834x over previous
#include <cuda_runtime.h>
#include <cuda_bf16.h>

#define NN 100000
#define EE 1600000
#define HD 128
#define FIN 64
#define NLAYER 3
#define SCAN_BLK 1024
#define NSCAN ((NN + SCAN_BLK - 1) / SCAN_BLK)   // 98

// ---------------- device scratch ----------------
__device__ float g_dinv[NN];
__device__ int   g_cnt[NN];        // per-dst edge count (no self loop)
__device__ int   g_rowptr[NN + 1];
__device__ int   g_cursor[NN];
__device__ int   g_blocksum[NSCAN + 1];
__device__ int   g_csr_src[EE];
__device__ float g_csr_w[EE];
__device__ float g_buf0[(size_t)NN * HD];
__device__ float g_buf1[(size_t)NN * HD];

// ---------------- degree / norm / CSR build ----------------
__global__ void k_zero_cnt() {
    int i = blockIdx.x * blockDim.x + threadIdx.x;
    if (i < NN) { g_cnt[i] = 0; g_cursor[i] = 0; }
}
__global__ void k_hist(const int* __restrict__ dst) {
    int e = blockIdx.x * blockDim.x + threadIdx.x;
    if (e < EE) atomicAdd(&g_cnt[dst[e]], 1);
}
__global__ void k_dinv() {
    int i = blockIdx.x * blockDim.x + threadIdx.x;
    if (i < NN) g_dinv[i] = rsqrtf((float)(g_cnt[i] + 1));  // +1 self loop
}
// block-wise inclusive scan -> exclusive row_ptr (no block offset yet)
__global__ void k_scan1() {
    __shared__ int sh[SCAN_BLK];
    int i = blockIdx.x * SCAN_BLK + threadIdx.x;
    int v = (i < NN) ? g_cnt[i] : 0;
    sh[threadIdx.x] = v;
    __syncthreads();
    int acc = v;
#pragma unroll
    for (int off = 1; off < SCAN_BLK; off <<= 1) {
        int t = (threadIdx.x >= off) ? sh[threadIdx.x - off] : 0;
        __syncthreads();
        acc += t;
        sh[threadIdx.x] = acc;
        __syncthreads();
    }
    if (i < NN) g_rowptr[i] = acc - v;   // exclusive within block
    if (threadIdx.x == SCAN_BLK - 1) g_blocksum[blockIdx.x] = acc;
}
__global__ void k_scan2() {   // single block, scan NSCAN block sums (exclusive)
    __shared__ int sh[128];
    int i = threadIdx.x;
    int v = (i < NSCAN) ? g_blocksum[i] : 0;
    sh[i] = v;
    __syncthreads();
    int acc = v;
#pragma unroll
    for (int off = 1; off < 128; off <<= 1) {
        int t = (i >= off) ? sh[i - off] : 0;
        __syncthreads();
        acc += t;
        sh[i] = acc;
        __syncthreads();
    }
    if (i < NSCAN) g_blocksum[i] = acc - v;  // exclusive
}
__global__ void k_scan3() {
    int i = blockIdx.x * blockDim.x + threadIdx.x;
    if (i < NN) g_rowptr[i] += g_blocksum[i / SCAN_BLK];
    if (i == 0) g_rowptr[NN] = EE;
}
__global__ void k_scatter(const int* __restrict__ src, const int* __restrict__ dst) {
    int e = blockIdx.x * blockDim.x + threadIdx.x;
    if (e >= EE) return;
    int s = src[e], d = dst[e];
    int pos = g_rowptr[d] + atomicAdd(&g_cursor[d], 1);
    g_csr_src[pos] = s;
    g_csr_w[pos] = g_dinv[s] * g_dinv[d];
}

// ---------------- gather aggregation ----------------
// F=128: one warp per node, lane owns one float4 column
__global__ void __launch_bounds__(256)
k_agg128(const float* __restrict__ in, float* __restrict__ out) {
    int node = blockIdx.x * 8 + (threadIdx.x >> 5);
    int lane = threadIdx.x & 31;
    if (node >= NN) return;
    const float4* in4 = (const float4*)in;
    float di = g_dinv[node];
    float4 a = in4[(size_t)node * 32 + lane];
    float w = di * di;
    float4 acc = make_float4(a.x * w, a.y * w, a.z * w, a.w * w);
    int j = g_rowptr[node], end = g_rowptr[node + 1];
    for (; j + 1 < end; j += 2) {
        int s0 = g_csr_src[j], s1 = g_csr_src[j + 1];
        float w0 = g_csr_w[j], w1 = g_csr_w[j + 1];
        float4 v0 = in4[(size_t)s0 * 32 + lane];
        float4 v1 = in4[(size_t)s1 * 32 + lane];
        acc.x += v0.x * w0 + v1.x * w1;
        acc.y += v0.y * w0 + v1.y * w1;
        acc.z += v0.z * w0 + v1.z * w1;
        acc.w += v0.w * w0 + v1.w * w1;
    }
    if (j < end) {
        int s0 = g_csr_src[j];
        float w0 = g_csr_w[j];
        float4 v0 = in4[(size_t)s0 * 32 + lane];
        acc.x += v0.x * w0; acc.y += v0.y * w0;
        acc.z += v0.z * w0; acc.w += v0.w * w0;
    }
    ((float4*)out)[(size_t)node * 32 + lane] = acc;
}
// F=64: one warp per node, lane owns one float2 column
__global__ void __launch_bounds__(256)
k_agg64(const float* __restrict__ in, float* __restrict__ out) {
    int node = blockIdx.x * 8 + (threadIdx.x >> 5);
    int lane = threadIdx.x & 31;
    if (node >= NN) return;
    const float2* in2 = (const float2*)in;
    float di = g_dinv[node];
    float2 a = in2[(size_t)node * 32 + lane];
    float w = di * di;
    float2 acc = make_float2(a.x * w, a.y * w);
    int j = g_rowptr[node], end = g_rowptr[node + 1];
    for (; j + 1 < end; j += 2) {
        int s0 = g_csr_src[j], s1 = g_csr_src[j + 1];
        float w0 = g_csr_w[j], w1 = g_csr_w[j + 1];
        float2 v0 = in2[(size_t)s0 * 32 + lane];
        float2 v1 = in2[(size_t)s1 * 32 + lane];
        acc.x += v0.x * w0 + v1.x * w1;
        acc.y += v0.y * w0 + v1.y * w1;
    }
    if (j < end) {
        int s0 = g_csr_src[j];
        float w0 = g_csr_w[j];
        float2 v0 = in2[(size_t)s0 * 32 + lane];
        acc.x += v0.x * w0; acc.y += v0.y * w0;
    }
    ((float2*)out)[(size_t)node * 32 + lane] = acc;
}

// ---------------- SGEMM: C[N,128] = A[N,K] @ W[K,128] + bias, relu ----------------
template <int K>
__global__ void __launch_bounds__(256, 2)
k_gemm(const float* __restrict__ A, const float* __restrict__ W,
       const float* __restrict__ bias, float* __restrict__ C, int do_relu) {
    __shared__ float As[16][128];
    __shared__ float Bs[16][128];
    int tid = threadIdx.x;
    int row0 = blockIdx.x * 128;
    int tr = (tid >> 4) * 8;
    int tc = (tid & 15) * 8;

    float acc[8][8];
#pragma unroll
    for (int i = 0; i < 8; i++)
#pragma unroll
        for (int j = 0; j < 8; j++) acc[i][j] = 0.0f;

    for (int k0 = 0; k0 < K; k0 += 16) {
#pragma unroll
        for (int i = 0; i < 2; i++) {
            int li = tid + i * 256;
            int r = li >> 2;
            int kk = (li & 3) * 4;
            float4 v = make_float4(0.f, 0.f, 0.f, 0.f);
            int gr = row0 + r;
            if (gr < NN) v = *(const float4*)(A + (size_t)gr * K + k0 + kk);
            As[kk + 0][r] = v.x; As[kk + 1][r] = v.y;
            As[kk + 2][r] = v.z; As[kk + 3][r] = v.w;
        }
#pragma unroll
        for (int i = 0; i < 2; i++) {
            int li = tid + i * 256;
            int kk = li >> 5;
            int n4 = (li & 31) * 4;
            *(float4*)&Bs[kk][n4] = *(const float4*)(W + (size_t)(k0 + kk) * 128 + n4);
        }
        __syncthreads();
#pragma unroll
        for (int k = 0; k < 16; k++) {
            float ra[8], rb[8];
            *(float4*)&ra[0] = *(const float4*)&As[k][tr];
            *(float4*)&ra[4] = *(const float4*)&As[k][tr + 4];
            *(float4*)&rb[0] = *(const float4*)&Bs[k][tc];
            *(float4*)&rb[4] = *(const float4*)&Bs[k][tc + 4];
#pragma unroll
            for (int i = 0; i < 8; i++)
#pragma unroll
                for (int j = 0; j < 8; j++) acc[i][j] += ra[i] * rb[j];
        }
        __syncthreads();
    }
#pragma unroll
    for (int i = 0; i < 8; i++) {
        int gr = row0 + tr + i;
        if (gr >= NN) continue;
#pragma unroll
        for (int j = 0; j < 8; j += 4) {
            float4 v;
            v.x = acc[i][j + 0] + bias[tc + j + 0];
            v.y = acc[i][j + 1] + bias[tc + j + 1];
            v.z = acc[i][j + 2] + bias[tc + j + 2];
            v.w = acc[i][j + 3] + bias[tc + j + 3];
            if (do_relu) {
                v.x = fmaxf(v.x, 0.f); v.y = fmaxf(v.y, 0.f);
                v.z = fmaxf(v.z, 0.f); v.w = fmaxf(v.w, 0.f);
            }
            *(float4*)(C + (size_t)gr * 128 + tc + j) = v;
        }
    }
}

// ---------------- final layer: matvec (128 -> 1), then F=1 gather ----------------
__global__ void k_matvec(const float* __restrict__ A, const float* __restrict__ W3,
                         float* __restrict__ out) {
    __shared__ float w[128];
    int tid = threadIdx.x;
    if (tid < 128) w[tid] = W3[tid];
    __syncthreads();
    int row = blockIdx.x * 8 + (tid >> 5);
    int lane = tid & 31;
    if (row >= NN) return;
    const float* a = A + (size_t)row * 128;
    float s = a[lane] * w[lane] + a[lane + 32] * w[lane + 32]
            + a[lane + 64] * w[lane + 64] + a[lane + 96] * w[lane + 96];
#pragma unroll
    for (int off = 16; off > 0; off >>= 1) s += __shfl_down_sync(0xffffffffu, s, off);
    if (lane == 0) out[row] = s;
}

__global__ void k_final(const float* __restrict__ t, const float* __restrict__ b3,
                        float* __restrict__ out) {
    int i = blockIdx.x * blockDim.x + threadIdx.x;
    if (i >= NN) return;
    float di = g_dinv[i];
    float s = t[i] * di * di + b3[0];
    int j = g_rowptr[i], end = g_rowptr[i + 1];
    for (; j < end; j++) s += t[g_csr_src[j]] * g_csr_w[j];
    out[i] = s;
}

// ---------------- launch ----------------
extern "C" void kernel_launch(void* const* d_in, const int* in_sizes, int n_in,
                              void* d_out, int out_size) {
    const float* x  = (const float*)d_in[0];
    const int* ei   = (const int*)d_in[1];
    const float* W1 = (const float*)d_in[2];
    const float* b1 = (const float*)d_in[3];
    const float* W2 = (const float*)d_in[4];
    const float* b2 = (const float*)d_in[5];
    const float* W3 = (const float*)d_in[6];
    const float* b3 = (const float*)d_in[7];
    float* out = (float*)d_out;

    const int* src = ei;
    const int* dst = ei + EE;

    float* buf0;  cudaGetSymbolAddress((void**)&buf0, g_buf0);
    float* buf1;  cudaGetSymbolAddress((void**)&buf1, g_buf1);

    // CSR build + norm
    k_zero_cnt<<<(NN + 255) / 256, 256>>>();
    k_hist<<<(EE + 255) / 256, 256>>>(dst);
    k_dinv<<<(NN + 255) / 256, 256>>>();
    k_scan1<<<NSCAN, SCAN_BLK>>>();
    k_scan2<<<1, 128>>>();
    k_scan3<<<(NN + 255) / 256, 256>>>();
    k_scatter<<<(EE + 255) / 256, 256>>>(src, dst);

    // layer 1: gather-aggregate x at F=64, then GEMM 64->128
    k_agg64<<<(NN + 7) / 8, 256>>>(x, buf0);
    k_gemm<FIN><<<(NN + 127) / 128, 256>>>(buf0, W1, b1, buf1, 1);

    // hidden layers
    for (int l = 0; l < NLAYER; l++) {
        k_agg128<<<(NN + 7) / 8, 256>>>(buf1, buf0);
        k_gemm<HD><<<(NN + 127) / 128, 256>>>(buf0, W2 + (size_t)l * HD * HD,
                                              b2 + (size_t)l * HD, buf1, 1);
    }

    // final layer: matvec first, then F=1 gather
    k_matvec<<<(NN + 7) / 8, 256>>>(buf1, W3, buf0);
    k_final<<<(NN + 255) / 256, 256>>>(buf0, b3, out);
}

// round 3
// speedup vs baseline: 2.1260x; 1.1288x over previous
#include <cuda_runtime.h>
#include <cuda_bf16.h>
#include <cstdint>

#define NN 100000
#define EE 1600000
#define HD 128
#define FIN 64
#define NLAYER 3
#define SCAN_BLK 1024
#define NSCAN ((NN + SCAN_BLK - 1) / SCAN_BLK)   // 98
#define NWELEM (FIN * HD + NLAYER * HD * HD)     // 57344

// ---------------- device scratch ----------------
__device__ float g_dinv[NN];
__device__ int   g_cnt[NN];
__device__ int   g_rowptr[NN + 1];
__device__ int   g_cursor[NN];
__device__ int   g_blocksum[NSCAN + 1];
__device__ int   g_csr_src[EE];
__device__ float g_csr_w[EE];
__device__ float g_buf0[(size_t)NN * HD];
__device__ float g_buf1[(size_t)NN * HD];
__device__ float g_Whi[NWELEM];
__device__ float g_Wlo[NWELEM];

// ---------------- degree / norm / CSR build ----------------
__global__ void k_zero_cnt() {
    int i = blockIdx.x * blockDim.x + threadIdx.x;
    if (i < NN) { g_cnt[i] = 0; g_cursor[i] = 0; }
}
__global__ void k_hist(const int* __restrict__ dst) {
    int e = blockIdx.x * blockDim.x + threadIdx.x;
    if (e < EE) atomicAdd(&g_cnt[dst[e]], 1);
}
__global__ void k_dinv() {
    int i = blockIdx.x * blockDim.x + threadIdx.x;
    if (i < NN) g_dinv[i] = rsqrtf((float)(g_cnt[i] + 1));
}
__global__ void k_scan1() {
    __shared__ int sh[SCAN_BLK];
    int i = blockIdx.x * SCAN_BLK + threadIdx.x;
    int v = (i < NN) ? g_cnt[i] : 0;
    sh[threadIdx.x] = v;
    __syncthreads();
    int acc = v;
#pragma unroll
    for (int off = 1; off < SCAN_BLK; off <<= 1) {
        int t = (threadIdx.x >= off) ? sh[threadIdx.x - off] : 0;
        __syncthreads();
        acc += t;
        sh[threadIdx.x] = acc;
        __syncthreads();
    }
    if (i < NN) g_rowptr[i] = acc - v;
    if (threadIdx.x == SCAN_BLK - 1) g_blocksum[blockIdx.x] = acc;
}
__global__ void k_scan2() {
    __shared__ int sh[128];
    int i = threadIdx.x;
    int v = (i < NSCAN) ? g_blocksum[i] : 0;
    sh[i] = v;
    __syncthreads();
    int acc = v;
#pragma unroll
    for (int off = 1; off < 128; off <<= 1) {
        int t = (i >= off) ? sh[i - off] : 0;
        __syncthreads();
        acc += t;
        sh[i] = acc;
        __syncthreads();
    }
    if (i < NSCAN) g_blocksum[i] = acc - v;
}
__global__ void k_scan3() {
    int i = blockIdx.x * blockDim.x + threadIdx.x;
    if (i < NN) g_rowptr[i] += g_blocksum[i / SCAN_BLK];
    if (i == 0) g_rowptr[NN] = EE;
}
__global__ void k_scatter(const int* __restrict__ src, const int* __restrict__ dst) {
    int e = blockIdx.x * blockDim.x + threadIdx.x;
    if (e >= EE) return;
    int s = src[e], d = dst[e];
    int pos = g_rowptr[d] + atomicAdd(&g_cursor[d], 1);
    g_csr_src[pos] = s;
    g_csr_w[pos] = g_dinv[s] * g_dinv[d];
}

// ---------------- weight split into tf32 hi/lo ----------------
__global__ void k_cvt_w(const float* __restrict__ W1, const float* __restrict__ W2) {
    int i = blockIdx.x * blockDim.x + threadIdx.x;
    if (i >= NWELEM) return;
    float v = (i < FIN * HD) ? W1[i] : W2[i - FIN * HD];
    uint32_t hi;
    asm("cvt.rna.tf32.f32 %0, %1;" : "=r"(hi) : "f"(v));
    float hf = __uint_as_float(hi);
    float lof = v - hf;
    uint32_t lo;
    asm("cvt.rna.tf32.f32 %0, %1;" : "=r"(lo) : "f"(lof));
    g_Whi[i] = hf;
    g_Wlo[i] = __uint_as_float(lo);
}

// ---------------- gather aggregation ----------------
__global__ void __launch_bounds__(256)
k_agg128(const float* __restrict__ in, float* __restrict__ out) {
    int node = blockIdx.x * 8 + (threadIdx.x >> 5);
    int lane = threadIdx.x & 31;
    if (node >= NN) return;
    const float4* in4 = (const float4*)in;
    float di = g_dinv[node];
    float4 a = in4[(size_t)node * 32 + lane];
    float w = di * di;
    float4 acc = make_float4(a.x * w, a.y * w, a.z * w, a.w * w);
    int j = g_rowptr[node], end = g_rowptr[node + 1];
    for (; j + 1 < end; j += 2) {
        int s0 = g_csr_src[j], s1 = g_csr_src[j + 1];
        float w0 = g_csr_w[j], w1 = g_csr_w[j + 1];
        float4 v0 = in4[(size_t)s0 * 32 + lane];
        float4 v1 = in4[(size_t)s1 * 32 + lane];
        acc.x += v0.x * w0 + v1.x * w1;
        acc.y += v0.y * w0 + v1.y * w1;
        acc.z += v0.z * w0 + v1.z * w1;
        acc.w += v0.w * w0 + v1.w * w1;
    }
    if (j < end) {
        int s0 = g_csr_src[j];
        float w0 = g_csr_w[j];
        float4 v0 = in4[(size_t)s0 * 32 + lane];
        acc.x += v0.x * w0; acc.y += v0.y * w0;
        acc.z += v0.z * w0; acc.w += v0.w * w0;
    }
    ((float4*)out)[(size_t)node * 32 + lane] = acc;
}
__global__ void __launch_bounds__(256)
k_agg64(const float* __restrict__ in, float* __restrict__ out) {
    int node = blockIdx.x * 8 + (threadIdx.x >> 5);
    int lane = threadIdx.x & 31;
    if (node >= NN) return;
    const float2* in2 = (const float2*)in;
    float di = g_dinv[node];
    float2 a = in2[(size_t)node * 32 + lane];
    float w = di * di;
    float2 acc = make_float2(a.x * w, a.y * w);
    int j = g_rowptr[node], end = g_rowptr[node + 1];
    for (; j + 1 < end; j += 2) {
        int s0 = g_csr_src[j], s1 = g_csr_src[j + 1];
        float w0 = g_csr_w[j], w1 = g_csr_w[j + 1];
        float2 v0 = in2[(size_t)s0 * 32 + lane];
        float2 v1 = in2[(size_t)s1 * 32 + lane];
        acc.x += v0.x * w0 + v1.x * w1;
        acc.y += v0.y * w0 + v1.y * w1;
    }
    if (j < end) {
        int s0 = g_csr_src[j];
        float w0 = g_csr_w[j];
        float2 v0 = in2[(size_t)s0 * 32 + lane];
        acc.x += v0.x * w0; acc.y += v0.y * w0;
    }
    ((float2*)out)[(size_t)node * 32 + lane] = acc;
}

// ---------------- tensor-core GEMM (3xTF32): C[N,128] = A[N,K]@W + bias, relu ----------------
#define MMA_TF32(d, a, b0, b1)                                              \
    asm volatile("mma.sync.aligned.m16n8k8.row.col.f32.tf32.tf32.f32 "      \
                 "{%0,%1,%2,%3}, {%4,%5,%6,%7}, {%8,%9}, {%0,%1,%2,%3};"    \
                 : "+f"(d[0]), "+f"(d[1]), "+f"(d[2]), "+f"(d[3])           \
                 : "r"(a[0]), "r"(a[1]), "r"(a[2]), "r"(a[3]),              \
                   "r"(b0), "r"(b1))

__device__ __forceinline__ void split_tf32(float v, uint32_t& hi, uint32_t& lo) {
    asm("cvt.rna.tf32.f32 %0, %1;" : "=r"(hi) : "f"(v));
    float l = v - __uint_as_float(hi);
    asm("cvt.rna.tf32.f32 %0, %1;" : "=r"(lo) : "f"(l));
}

#define GBK 16
#define A_STRIDE 20     // conflict-free for frag loads
#define B_STRIDE 132    // float2 row stride

template <int K>
__global__ void __launch_bounds__(256, 2)
k_gemm_tc(const float* __restrict__ A, const float* __restrict__ Whi,
          const float* __restrict__ Wlo, const float* __restrict__ bias,
          float* __restrict__ C, int do_relu) {
    __shared__ float  As[128 * A_STRIDE];
    __shared__ float2 Bhl[GBK * B_STRIDE];

    int tid = threadIdx.x;
    int wid = tid >> 5, lane = tid & 31;
    int wr = wid >> 1, wc = wid & 1;          // 4x2 warp grid
    int row0 = blockIdx.x * 128;
    int mrow = wr * 32;
    int ncol = wc * 64;
    int lq = lane >> 2;                        // lane/4 (0..7)
    int lr = lane & 3;                         // lane%4

    float acc[2][8][4];
#pragma unroll
    for (int ma = 0; ma < 2; ma++)
#pragma unroll
        for (int na = 0; na < 8; na++)
#pragma unroll
            for (int r = 0; r < 4; r++) acc[ma][na][r] = 0.0f;

    for (int k0 = 0; k0 < K; k0 += GBK) {
        // A tile: 128 rows x 16 k  (512 float4, 2/thread)
#pragma unroll
        for (int i = 0; i < 2; i++) {
            int li = tid + i * 256;
            int r = li >> 2;                   // 4 float4 per row
            int c4 = (li & 3) * 4;
            float4 v = make_float4(0.f, 0.f, 0.f, 0.f);
            int gr = row0 + r;
            if (gr < NN) v = *(const float4*)(A + (size_t)gr * K + k0 + c4);
            float* p = &As[r * A_STRIDE + c4];
            p[0] = v.x; p[1] = v.y; p[2] = v.z; p[3] = v.w;
        }
        // B tile: 16 k x 128 n, hi/lo interleaved (512 float4 each, 2/thread)
#pragma unroll
        for (int i = 0; i < 2; i++) {
            int li = tid + i * 256;
            int kk = li >> 5;                  // 32 float4 per row
            int n4 = (li & 31) * 4;
            float4 h = *(const float4*)(Whi + (size_t)(k0 + kk) * 128 + n4);
            float4 l = *(const float4*)(Wlo + (size_t)(k0 + kk) * 128 + n4);
            float2* p = &Bhl[kk * B_STRIDE + n4];
            p[0] = make_float2(h.x, l.x); p[1] = make_float2(h.y, l.y);
            p[2] = make_float2(h.z, l.z); p[3] = make_float2(h.w, l.w);
        }
        __syncthreads();
#pragma unroll
        for (int ks = 0; ks < GBK / 8; ks++) {
            // A fragments (2 m-atoms), split hi/lo
            uint32_t ah[2][4], al[2][4];
#pragma unroll
            for (int ma = 0; ma < 2; ma++) {
                int r = mrow + ma * 16 + lq;
                int c = ks * 8 + lr;
                split_tf32(As[r * A_STRIDE + c],            ah[ma][0], al[ma][0]);
                split_tf32(As[(r + 8) * A_STRIDE + c],      ah[ma][1], al[ma][1]);
                split_tf32(As[r * A_STRIDE + c + 4],        ah[ma][2], al[ma][2]);
                split_tf32(As[(r + 8) * A_STRIDE + c + 4],  ah[ma][3], al[ma][3]);
            }
#pragma unroll
            for (int na = 0; na < 8; na++) {
                int bk = ks * 8 + lr;
                int bn = ncol + na * 8 + lq;
                float2 b0 = Bhl[bk * B_STRIDE + bn];
                float2 b1 = Bhl[(bk + 4) * B_STRIDE + bn];
                uint32_t bh0 = __float_as_uint(b0.x), bl0 = __float_as_uint(b0.y);
                uint32_t bh1 = __float_as_uint(b1.x), bl1 = __float_as_uint(b1.y);
#pragma unroll
                for (int ma = 0; ma < 2; ma++) {
                    MMA_TF32(acc[ma][na], ah[ma], bh0, bh1);
                    MMA_TF32(acc[ma][na], ah[ma], bl0, bl1);
                    MMA_TF32(acc[ma][na], al[ma], bh0, bh1);
                }
            }
        }
        __syncthreads();
    }
    // epilogue: bias + relu
#pragma unroll
    for (int ma = 0; ma < 2; ma++) {
        int r0 = row0 + mrow + ma * 16 + lq;
#pragma unroll
        for (int na = 0; na < 8; na++) {
            int col = ncol + na * 8 + 2 * lr;
            float bx = bias[col], by = bias[col + 1];
            float2 v0 = make_float2(acc[ma][na][0] + bx, acc[ma][na][1] + by);
            float2 v1 = make_float2(acc[ma][na][2] + bx, acc[ma][na][3] + by);
            if (do_relu) {
                v0.x = fmaxf(v0.x, 0.f); v0.y = fmaxf(v0.y, 0.f);
                v1.x = fmaxf(v1.x, 0.f); v1.y = fmaxf(v1.y, 0.f);
            }
            if (r0 < NN)     *(float2*)(C + (size_t)r0 * 128 + col) = v0;
            if (r0 + 8 < NN) *(float2*)(C + (size_t)(r0 + 8) * 128 + col) = v1;
        }
    }
}

// ---------------- final layer: matvec (128 -> 1), then F=1 gather ----------------
__global__ void k_matvec(const float* __restrict__ A, const float* __restrict__ W3,
                         float* __restrict__ out) {
    __shared__ float w[128];
    int tid = threadIdx.x;
    if (tid < 128) w[tid] = W3[tid];
    __syncthreads();
    int row = blockIdx.x * 8 + (tid >> 5);
    int lane = tid & 31;
    if (row >= NN) return;
    const float* a = A + (size_t)row * 128;
    float s = a[lane] * w[lane] + a[lane + 32] * w[lane + 32]
            + a[lane + 64] * w[lane + 64] + a[lane + 96] * w[lane + 96];
#pragma unroll
    for (int off = 16; off > 0; off >>= 1) s += __shfl_down_sync(0xffffffffu, s, off);
    if (lane == 0) out[row] = s;
}

__global__ void k_final(const float* __restrict__ t, const float* __restrict__ b3,
                        float* __restrict__ out) {
    int i = blockIdx.x * blockDim.x + threadIdx.x;
    if (i >= NN) return;
    float di = g_dinv[i];
    float s = t[i] * di * di + b3[0];
    int j = g_rowptr[i], end = g_rowptr[i + 1];
    for (; j < end; j++) s += t[g_csr_src[j]] * g_csr_w[j];
    out[i] = s;
}

// ---------------- launch ----------------
extern "C" void kernel_launch(void* const* d_in, const int* in_sizes, int n_in,
                              void* d_out, int out_size) {
    const float* x  = (const float*)d_in[0];
    const int* ei   = (const int*)d_in[1];
    const float* W1 = (const float*)d_in[2];
    const float* b1 = (const float*)d_in[3];
    const float* W2 = (const float*)d_in[4];
    const float* b2 = (const float*)d_in[5];
    const float* W3 = (const float*)d_in[6];
    const float* b3 = (const float*)d_in[7];
    float* out = (float*)d_out;

    const int* src = ei;
    const int* dst = ei + EE;

    float* buf0;  cudaGetSymbolAddress((void**)&buf0, g_buf0);
    float* buf1;  cudaGetSymbolAddress((void**)&buf1, g_buf1);
    float* whi;   cudaGetSymbolAddress((void**)&whi, g_Whi);
    float* wlo;   cudaGetSymbolAddress((void**)&wlo, g_Wlo);

    // CSR build + norm + weight split
    k_zero_cnt<<<(NN + 255) / 256, 256>>>();
    k_hist<<<(EE + 255) / 256, 256>>>(dst);
    k_cvt_w<<<(NWELEM + 255) / 256, 256>>>(W1, W2);
    k_dinv<<<(NN + 255) / 256, 256>>>();
    k_scan1<<<NSCAN, SCAN_BLK>>>();
    k_scan2<<<1, 128>>>();
    k_scan3<<<(NN + 255) / 256, 256>>>();
    k_scatter<<<(EE + 255) / 256, 256>>>(src, dst);

    // layer 1: gather-aggregate x at F=64, then GEMM 64->128
    k_agg64<<<(NN + 7) / 8, 256>>>(x, buf0);
    k_gemm_tc<FIN><<<(NN + 127) / 128, 256>>>(buf0, whi, wlo, b1, buf1, 1);

    // hidden layers
    for (int l = 0; l < NLAYER; l++) {
        k_agg128<<<(NN + 7) / 8, 256>>>(buf1, buf0);
        k_gemm_tc<HD><<<(NN + 127) / 128, 256>>>(
            buf0, whi + FIN * HD + (size_t)l * HD * HD,
            wlo + FIN * HD + (size_t)l * HD * HD,
            b2 + (size_t)l * HD, buf1, 1);
    }

    // final layer: matvec first, then F=1 gather
    k_matvec<<<(NN + 7) / 8, 256>>>(buf1, W3, buf0);
    k_final<<<(NN + 255) / 256, 256>>>(buf0, b3, out);
}

// round 4
// speedup vs baseline: 2.9865x; 1.4047x over previous
#include <cuda_runtime.h>
#include <cuda_fp16.h>
#include <cstdint>

#define NN 100000
#define EE 1600000
#define HD 128
#define FIN 64
#define NLAYER 3
#define SCAN_BLK 1024
#define NSCAN ((NN + SCAN_BLK - 1) / SCAN_BLK)   // 98
#define NWELEM (FIN * HD + NLAYER * HD * HD)     // 57344

// ---------------- device scratch ----------------
__device__ float  g_dinv[NN];
__device__ int    g_cnt[NN];
__device__ int    g_rowptr[NN + 1];
__device__ int    g_cursor[NN];
__device__ int    g_blocksum[NSCAN + 1];
__device__ int    g_csr_src[EE];
__device__ float  g_csr_w[EE];
__device__ float  g_t[NN];                 // final matvec output
__device__ __half g_x16[(size_t)NN * FIN];
__device__ __half g_h16[(size_t)NN * HD];
__device__ __half g_g16[(size_t)NN * HD];
__device__ __half g_WhiT[NWELEM];          // transposed [n][k] fp16 hi
__device__ __half g_WloT[NWELEM];          // transposed [n][k] fp16 lo

// ---------------- degree / norm / CSR build ----------------
__global__ void k_zero_cnt() {
    int i = blockIdx.x * blockDim.x + threadIdx.x;
    if (i < NN) { g_cnt[i] = 0; g_cursor[i] = 0; }
}
__global__ void k_hist(const int* __restrict__ dst) {
    int e = blockIdx.x * blockDim.x + threadIdx.x;
    if (e < EE) atomicAdd(&g_cnt[dst[e]], 1);
}
__global__ void k_dinv() {
    int i = blockIdx.x * blockDim.x + threadIdx.x;
    if (i < NN) g_dinv[i] = rsqrtf((float)(g_cnt[i] + 1));
}
__global__ void k_scan1() {
    __shared__ int sh[SCAN_BLK];
    int i = blockIdx.x * SCAN_BLK + threadIdx.x;
    int v = (i < NN) ? g_cnt[i] : 0;
    sh[threadIdx.x] = v;
    __syncthreads();
    int acc = v;
#pragma unroll
    for (int off = 1; off < SCAN_BLK; off <<= 1) {
        int t = (threadIdx.x >= off) ? sh[threadIdx.x - off] : 0;
        __syncthreads();
        acc += t;
        sh[threadIdx.x] = acc;
        __syncthreads();
    }
    if (i < NN) g_rowptr[i] = acc - v;
    if (threadIdx.x == SCAN_BLK - 1) g_blocksum[blockIdx.x] = acc;
}
__global__ void k_scan2() {
    __shared__ int sh[128];
    int i = threadIdx.x;
    int v = (i < NSCAN) ? g_blocksum[i] : 0;
    sh[i] = v;
    __syncthreads();
    int acc = v;
#pragma unroll
    for (int off = 1; off < 128; off <<= 1) {
        int t = (i >= off) ? sh[i - off] : 0;
        __syncthreads();
        acc += t;
        sh[i] = acc;
        __syncthreads();
    }
    if (i < NSCAN) g_blocksum[i] = acc - v;
}
__global__ void k_scan3() {
    int i = blockIdx.x * blockDim.x + threadIdx.x;
    if (i < NN) g_rowptr[i] += g_blocksum[i / SCAN_BLK];
    if (i == 0) g_rowptr[NN] = EE;
}
__global__ void k_scatter(const int* __restrict__ src, const int* __restrict__ dst) {
    int e = blockIdx.x * blockDim.x + threadIdx.x;
    if (e >= EE) return;
    int s = src[e], d = dst[e];
    int pos = g_rowptr[d] + atomicAdd(&g_cursor[d], 1);
    g_csr_src[pos] = s;
    g_csr_w[pos] = g_dinv[s] * g_dinv[d];
}

// ---------------- conversions ----------------
__global__ void k_cvt_x(const float* __restrict__ x) {
    int i = blockIdx.x * blockDim.x + threadIdx.x;
    if (i < NN * FIN) g_x16[i] = __float2half_rn(x[i]);
}
// split weights into fp16 hi/lo, transposed to [n][k]
__global__ void k_cvt_w(const float* __restrict__ W1, const float* __restrict__ W2) {
    int i = blockIdx.x * blockDim.x + threadIdx.x;
    if (i >= NWELEM) return;
    float v;
    int oidx;
    if (i < FIN * HD) {                    // W1[k][n], k<64, n<128 -> T[n*64+k]
        int k = i / HD, n = i % HD;
        v = W1[i];
        oidx = n * FIN + k;
    } else {
        int j = i - FIN * HD;
        int l = j / (HD * HD), r = j % (HD * HD);
        int k = r / HD, n = r % HD;
        v = W2[j];
        oidx = FIN * HD + l * HD * HD + n * HD + k;
    }
    __half hi = __float2half_rn(v);
    float lof = v - __half2float(hi);
    g_WhiT[oidx] = hi;
    g_WloT[oidx] = __float2half_rn(lof);
}

// ---------------- fp16 tensor-core GEMM: g[N,128] = h[N,K] @ W[K,128] ----------------
// A fp16 exact, B = Whi + Wlo (2 MMAs). No bias/relu (fused into aggregation).
#define MMA_F16(d, a0, a1, a2, a3, b0, b1)                                  \
    asm volatile("mma.sync.aligned.m16n8k16.row.col.f32.f16.f16.f32 "       \
                 "{%0,%1,%2,%3}, {%4,%5,%6,%7}, {%8,%9}, {%0,%1,%2,%3};"    \
                 : "+f"(d[0]), "+f"(d[1]), "+f"(d[2]), "+f"(d[3])           \
                 : "r"(a0), "r"(a1), "r"(a2), "r"(a3), "r"(b0), "r"(b1))

#define AST 40   // smem stride in halves for 32-k tiles (conflict-free)

template <int K>
__global__ void __launch_bounds__(256, 2)
k_gemm16(const __half* __restrict__ A, const __half* __restrict__ BhiT,
         const __half* __restrict__ BloT, __half* __restrict__ Cout) {
    __shared__ __half As[128 * AST];
    __shared__ __half Bhi[128 * AST];
    __shared__ __half Blo[128 * AST];

    int tid = threadIdx.x;
    int wid = tid >> 5, lane = tid & 31;
    int wr = wid >> 1, wc = wid & 1;
    int row0 = blockIdx.x * 128;
    int mrow = wr * 32;
    int ncol = wc * 64;
    int lq = lane >> 2;
    int lr = lane & 3;

    float acc[2][8][4];
#pragma unroll
    for (int ma = 0; ma < 2; ma++)
#pragma unroll
        for (int na = 0; na < 8; na++)
#pragma unroll
            for (int r = 0; r < 4; r++) acc[ma][na][r] = 0.0f;

    for (int k0 = 0; k0 < K; k0 += 32) {
        // A tile: 128 rows x 32 halves (512 x 16B, 2/thread)
#pragma unroll
        for (int i = 0; i < 2; i++) {
            int li = tid + i * 256;
            int r = li >> 2;
            int c = (li & 3) * 8;          // halves
            uint4 v = make_uint4(0, 0, 0, 0);
            int gr = row0 + r;
            if (gr < NN) v = *(const uint4*)(A + (size_t)gr * K + k0 + c);
            *(uint4*)&As[r * AST + c] = v;
        }
        // B tiles: 128 n-rows x 32 k halves per plane
#pragma unroll
        for (int i = 0; i < 2; i++) {
            int li = tid + i * 256;
            int n = li >> 2;
            int c = (li & 3) * 8;
            *(uint4*)&Bhi[n * AST + c] = *(const uint4*)(BhiT + (size_t)n * K + k0 + c);
            *(uint4*)&Blo[n * AST + c] = *(const uint4*)(BloT + (size_t)n * K + k0 + c);
        }
        __syncthreads();
#pragma unroll
        for (int ks = 0; ks < 2; ks++) {
            int kk = ks * 16;
            uint32_t a[2][4];
#pragma unroll
            for (int ma = 0; ma < 2; ma++) {
                int rb = mrow + ma * 16;
                a[ma][0] = *(const uint32_t*)&As[(rb + lq) * AST + kk + 2 * lr];
                a[ma][1] = *(const uint32_t*)&As[(rb + lq + 8) * AST + kk + 2 * lr];
                a[ma][2] = *(const uint32_t*)&As[(rb + lq) * AST + kk + 2 * lr + 8];
                a[ma][3] = *(const uint32_t*)&As[(rb + lq + 8) * AST + kk + 2 * lr + 8];
            }
#pragma unroll
            for (int na = 0; na < 8; na++) {
                int n = ncol + na * 8 + lq;
                uint32_t bh0 = *(const uint32_t*)&Bhi[n * AST + kk + 2 * lr];
                uint32_t bh1 = *(const uint32_t*)&Bhi[n * AST + kk + 2 * lr + 8];
                uint32_t bl0 = *(const uint32_t*)&Blo[n * AST + kk + 2 * lr];
                uint32_t bl1 = *(const uint32_t*)&Blo[n * AST + kk + 2 * lr + 8];
#pragma unroll
                for (int ma = 0; ma < 2; ma++) {
                    MMA_F16(acc[ma][na], a[ma][0], a[ma][1], a[ma][2], a[ma][3], bh0, bh1);
                    MMA_F16(acc[ma][na], a[ma][0], a[ma][1], a[ma][2], a[ma][3], bl0, bl1);
                }
            }
        }
        __syncthreads();
    }
    // epilogue: store fp16 g
#pragma unroll
    for (int ma = 0; ma < 2; ma++) {
        int r0 = row0 + mrow + ma * 16 + lq;
#pragma unroll
        for (int na = 0; na < 8; na++) {
            int col = ncol + na * 8 + 2 * lr;
            __half2 v0 = __floats2half2_rn(acc[ma][na][0], acc[ma][na][1]);
            __half2 v1 = __floats2half2_rn(acc[ma][na][2], acc[ma][na][3]);
            if (r0 < NN)     *(__half2*)(Cout + (size_t)r0 * 128 + col) = v0;
            if (r0 + 8 < NN) *(__half2*)(Cout + (size_t)(r0 + 8) * 128 + col) = v1;
        }
    }
}

// ---------------- fp16 gather aggregation + bias + relu ----------------
// one warp per node; lane owns 4 halves (8 bytes)
__global__ void __launch_bounds__(256)
k_agg16(const __half* __restrict__ in, const float* __restrict__ bias,
        __half* __restrict__ out) {
    int node = blockIdx.x * 8 + (threadIdx.x >> 5);
    int lane = threadIdx.x & 31;
    if (node >= NN) return;
    const uint2* in2 = (const uint2*)in;
    float di = g_dinv[node];
    float w = di * di;
    uint2 sv = in2[(size_t)node * 32 + lane];
    __half2 p0 = *reinterpret_cast<__half2*>(&sv.x);
    __half2 p1 = *reinterpret_cast<__half2*>(&sv.y);
    float2 f0 = __half22float2(p0), f1 = __half22float2(p1);
    float a0 = f0.x * w, a1 = f0.y * w, a2 = f1.x * w, a3 = f1.y * w;

    int j = g_rowptr[node], end = g_rowptr[node + 1];
    for (; j + 1 < end; j += 2) {
        int s0 = g_csr_src[j], s1 = g_csr_src[j + 1];
        float w0 = g_csr_w[j], w1 = g_csr_w[j + 1];
        uint2 v0 = in2[(size_t)s0 * 32 + lane];
        uint2 v1 = in2[(size_t)s1 * 32 + lane];
        float2 u0 = __half22float2(*reinterpret_cast<__half2*>(&v0.x));
        float2 u1 = __half22float2(*reinterpret_cast<__half2*>(&v0.y));
        float2 u2 = __half22float2(*reinterpret_cast<__half2*>(&v1.x));
        float2 u3 = __half22float2(*reinterpret_cast<__half2*>(&v1.y));
        a0 += u0.x * w0 + u2.x * w1;
        a1 += u0.y * w0 + u2.y * w1;
        a2 += u1.x * w0 + u3.x * w1;
        a3 += u1.y * w0 + u3.y * w1;
    }
    if (j < end) {
        int s0 = g_csr_src[j];
        float w0 = g_csr_w[j];
        uint2 v0 = in2[(size_t)s0 * 32 + lane];
        float2 u0 = __half22float2(*reinterpret_cast<__half2*>(&v0.x));
        float2 u1 = __half22float2(*reinterpret_cast<__half2*>(&v0.y));
        a0 += u0.x * w0; a1 += u0.y * w0; a2 += u1.x * w0; a3 += u1.y * w0;
    }
    float4 b = *(const float4*)(bias + lane * 4);
    a0 = fmaxf(a0 + b.x, 0.f); a1 = fmaxf(a1 + b.y, 0.f);
    a2 = fmaxf(a2 + b.z, 0.f); a3 = fmaxf(a3 + b.w, 0.f);
    __half2 o0 = __floats2half2_rn(a0, a1);
    __half2 o1 = __floats2half2_rn(a2, a3);
    uint2 ov;
    ov.x = *reinterpret_cast<uint32_t*>(&o0);
    ov.y = *reinterpret_cast<uint32_t*>(&o1);
    ((uint2*)out)[(size_t)node * 32 + lane] = ov;
}

// ---------------- final layer: matvec (fp16 h, fp32 W3), then F=1 gather ----------------
__global__ void k_matvec(const __half* __restrict__ A, const float* __restrict__ W3,
                         float* __restrict__ out) {
    __shared__ float w[128];
    int tid = threadIdx.x;
    if (tid < 128) w[tid] = W3[tid];
    __syncthreads();
    int row = blockIdx.x * 8 + (tid >> 5);
    int lane = tid & 31;
    if (row >= NN) return;
    const __half* a = A + (size_t)row * 128;
    float s = __half2float(a[lane]) * w[lane]
            + __half2float(a[lane + 32]) * w[lane + 32]
            + __half2float(a[lane + 64]) * w[lane + 64]
            + __half2float(a[lane + 96]) * w[lane + 96];
#pragma unroll
    for (int off = 16; off > 0; off >>= 1) s += __shfl_down_sync(0xffffffffu, s, off);
    if (lane == 0) out[row] = s;
}

__global__ void k_final(const float* __restrict__ t, const float* __restrict__ b3,
                        float* __restrict__ out) {
    int i = blockIdx.x * blockDim.x + threadIdx.x;
    if (i >= NN) return;
    float di = g_dinv[i];
    float s = t[i] * di * di + b3[0];
    int j = g_rowptr[i], end = g_rowptr[i + 1];
    for (; j < end; j++) s += t[g_csr_src[j]] * g_csr_w[j];
    out[i] = s;
}

// ---------------- launch ----------------
extern "C" void kernel_launch(void* const* d_in, const int* in_sizes, int n_in,
                              void* d_out, int out_size) {
    const float* x  = (const float*)d_in[0];
    const int* ei   = (const int*)d_in[1];
    const float* W1 = (const float*)d_in[2];
    const float* b1 = (const float*)d_in[3];
    const float* W2 = (const float*)d_in[4];
    const float* b2 = (const float*)d_in[5];
    const float* W3 = (const float*)d_in[6];
    const float* b3 = (const float*)d_in[7];
    float* out = (float*)d_out;

    const int* src = ei;
    const int* dst = ei + EE;

    __half* x16;  cudaGetSymbolAddress((void**)&x16, g_x16);
    __half* h16;  cudaGetSymbolAddress((void**)&h16, g_h16);
    __half* g16;  cudaGetSymbolAddress((void**)&g16, g_g16);
    __half* whiT; cudaGetSymbolAddress((void**)&whiT, g_WhiT);
    __half* wloT; cudaGetSymbolAddress((void**)&wloT, g_WloT);
    float* tbuf;  cudaGetSymbolAddress((void**)&tbuf, g_t);

    // CSR build + norm + conversions
    k_zero_cnt<<<(NN + 255) / 256, 256>>>();
    k_hist<<<(EE + 255) / 256, 256>>>(dst);
    k_cvt_w<<<(NWELEM + 255) / 256, 256>>>(W1, W2);
    k_cvt_x<<<(NN * FIN + 255) / 256, 256>>>(x);
    k_dinv<<<(NN + 255) / 256, 256>>>();
    k_scan1<<<NSCAN, SCAN_BLK>>>();
    k_scan2<<<1, 128>>>();
    k_scan3<<<(NN + 255) / 256, 256>>>();
    k_scatter<<<(EE + 255) / 256, 256>>>(src, dst);

    const int GB = (NN + 127) / 128;

    // layer 1: g = x @ W1 (GEMM-first), then aggregate + b1 + relu
    k_gemm16<FIN><<<GB, 256>>>(x16, whiT, wloT, g16);
    k_agg16<<<(NN + 7) / 8, 256>>>(g16, b1, h16);

    // hidden layers
    for (int l = 0; l < NLAYER; l++) {
        const __half* bh = whiT + FIN * HD + (size_t)l * HD * HD;
        const __half* bl = wloT + FIN * HD + (size_t)l * HD * HD;
        k_gemm16<HD><<<GB, 256>>>(h16, bh, bl, g16);
        k_agg16<<<(NN + 7) / 8, 256>>>(g16, b2 + (size_t)l * HD, h16);
    }

    // final layer: matvec, then F=1 gather + b3
    k_matvec<<<(NN + 7) / 8, 256>>>(h16, W3, tbuf);
    k_final<<<(NN + 255) / 256, 256>>>(tbuf, b3, out);
}